// round 15
// baseline (speedup 1.0000x reference)
#include <cuda_runtime.h>

#define BATCH 4096
#define FEAT  512
#define NUMC  10000

#define BLOCK_THREADS 256
#define WARPS_PER_BLOCK (BLOCK_THREADS / 32)        // 8
#define GRID_BLOCKS (BATCH / WARPS_PER_BLOCK)       // 512
#define TOTAL_WARPS BATCH                           // one warp per row

#define FIX_SCALE 67108864.0                        // 2^26 (Q.26 fixed point)
#define CNT_SHIFT 51
#define SUM_MASK  ((1ULL << CNT_SHIFT) - 1ULL)

// Scratch (no cudaMalloc allowed). Zero-init; reset by the last warp each run.
// bits [0,51)  = Q.26 fixed-point sum  (max ~2^49 < 2^51; int adds commutative)
// bits [51,64) = completed-warp counter (4096 * 2^51 = 2^63 < 2^64)
__device__ unsigned long long g_isum;

__global__ void __launch_bounds__(BLOCK_THREADS)
center_loss_kernel(const float* __restrict__ x,
                   const int*   __restrict__ labels32,
                   const float* __restrict__ centers,
                   float*       __restrict__ out) {
    const int lane = threadIdx.x & 31;
    const int wid  = threadIdx.x >> 5;
    const int row  = blockIdx.x * WARPS_PER_BLOCK + wid;

    // ---- all independent loads issued up front ------------------------------
    // dtype probe: odd words of first 64 int32 all zero <=> int64 labels.
    // P(false positive for int32 labels) = 1e-128. Fixed probe, every warp.
    int probe = __ldg(&labels32[2 * lane + 1]);
    int labA  = __ldg(&labels32[2 * row]);    // int64 candidate (low word)
    int labB  = __ldg(&labels32[row]);        // int32 candidate

    const float4* xr = reinterpret_cast<const float4*>(x + (size_t)row * FEAT);
    float4 xv[4];
#pragma unroll
    for (int i = 0; i < 4; i++) xv[i] = __ldg(&xr[lane + 32 * i]);

    bool is64 = (__ballot_sync(0xffffffffu, probe != 0) == 0u);
    int  lab  = is64 ? labA : labB;

    const float4* cr = reinterpret_cast<const float4*>(centers + (size_t)lab * FEAT);

    float a0 = 0.f, a1 = 0.f, a2 = 0.f, a3 = 0.f;
#pragma unroll
    for (int i = 0; i < 4; i++) {
        float4 cv = __ldg(&cr[lane + 32 * i]);
        float d0 = xv[i].x - cv.x;
        float d1 = xv[i].y - cv.y;
        float d2 = xv[i].z - cv.z;
        float d3 = xv[i].w - cv.w;
        a0 = fmaf(d0, d0, a0);
        a1 = fmaf(d1, d1, a1);
        a2 = fmaf(d2, d2, a2);
        a3 = fmaf(d3, d3, a3);
    }
    float acc = (a0 + a1) + (a2 + a3);
#pragma unroll
    for (int o = 16; o > 0; o >>= 1)
        acc += __shfl_xor_sync(0xffffffffu, acc, o);

    // ---- NO barrier, NO smem: each warp contributes and retires --------------
    if (lane == 0) {
        float c = fminf(fmaxf(acc, 1e-12f), 1e12f);   // clip diagonal entry

        // ONE packed atomic per warp: Q.26 sum + arrival counter.
        unsigned long long q =
            (unsigned long long)__double2ll_rn((double)c * FIX_SCALE);
        unsigned long long old =
            atomicAdd(&g_isum, q + (1ULL << CNT_SHIFT));

        if ((old >> CNT_SHIFT) == (unsigned long long)(TOTAL_WARPS - 1)) {
            // 4096th arrival: grand total already in hand — no read-back.
            unsigned long long tot = (old & SUM_MASK) + q;
            double t = (double)tot * (1.0 / FIX_SCALE);
            out[0] = (float)(t / (double)BATCH + (double)(NUMC - 1) * 1e-12);
            g_isum = 0ULL;   // replay-safe reset (all contributions landed)
        }
    }
}

extern "C" void kernel_launch(void* const* d_in, const int* in_sizes, int n_in,
                              void* d_out, int out_size) {
    const float* x       = (const float*)d_in[0];
    const int*   labels  = (const int*)  d_in[1];
    const float* centers = (const float*)d_in[2];
    float*       out     = (float*)d_out;

    center_loss_kernel<<<GRID_BLOCKS, BLOCK_THREADS>>>(x, labels, centers, out);
}

// round 16
// speedup vs baseline: 1.2706x; 1.2706x over previous
#include <cuda_runtime.h>

#define BATCH 4096
#define FEAT  512
#define NUMC  10000

#define BLOCK_THREADS 256
#define WARPS_PER_BLOCK (BLOCK_THREADS / 32)        // 8
#define GRID_BLOCKS (BATCH / WARPS_PER_BLOCK)       // 512

#define FIX_SCALE 67108864.0                        // 2^26 (Q.26 fixed point)
#define CNT_SHIFT 53
#define SUM_MASK  ((1ULL << CNT_SHIFT) - 1ULL)

// Scratch (no cudaMalloc allowed). Zero-init; reset by the last block each run.
// bits [0,53)  = Q.26 fixed-point sum (max ~2^48; integer adds commutative)
// bits [53,64) = completed-block counter (512 * 2^53 = 2^62 < 2^64)
__device__ unsigned long long g_isum;

// ---------------------------------------------------------------------------
// Loss = mean_b clip(||x_b - centers[label_b]||^2, 1e-12, 1e12)
//        + (NUMC-1)*1e-12   (the reference clips the masked zeros too)
//
// Single kernel, one warp per batch row:
//  - per-warp label-dtype detection (int64 vs int32) from a fixed 32-word probe
//  - gathered row-wise squared distance (fully coalesced float4 loads)
//  - block smem reduce -> ONE packed (count | Q.26 sum) atomicAdd per block;
//    integer adds are commutative -> bitwise-deterministic across replays
//  - the 512th-arriving block already holds the grand total in the atomic's
//    return value: writes the scalar and resets scratch (graph-replay safe)
// ---------------------------------------------------------------------------
__global__ void __launch_bounds__(BLOCK_THREADS)
center_loss_kernel(const float* __restrict__ x,
                   const int*   __restrict__ labels32,
                   const float* __restrict__ centers,
                   float*       __restrict__ out) {
    const int lane = threadIdx.x & 31;
    const int wid  = threadIdx.x >> 5;
    const int row  = blockIdx.x * WARPS_PER_BLOCK + wid;

    // ---- all independent loads issued up front ------------------------------
    // dtype probe: odd words of first 64 int32 all zero <=> int64 labels.
    // P(false positive for int32 labels) = 1e-128. Fixed probe, every warp.
    int probe = __ldg(&labels32[2 * lane + 1]);
    int labA  = __ldg(&labels32[2 * row]);    // int64 candidate (low word)
    int labB  = __ldg(&labels32[row]);        // int32 candidate

    const float4* xr = reinterpret_cast<const float4*>(x + (size_t)row * FEAT);
    float4 xv[4];
#pragma unroll
    for (int i = 0; i < 4; i++) xv[i] = __ldg(&xr[lane + 32 * i]);

    bool is64 = (__ballot_sync(0xffffffffu, probe != 0) == 0u);
    int  lab  = is64 ? labA : labB;

    const float4* cr = reinterpret_cast<const float4*>(centers + (size_t)lab * FEAT);

    float a0 = 0.f, a1 = 0.f, a2 = 0.f, a3 = 0.f;
#pragma unroll
    for (int i = 0; i < 4; i++) {
        float4 cv = __ldg(&cr[lane + 32 * i]);
        float d0 = xv[i].x - cv.x;
        float d1 = xv[i].y - cv.y;
        float d2 = xv[i].z - cv.z;
        float d3 = xv[i].w - cv.w;
        a0 = fmaf(d0, d0, a0);
        a1 = fmaf(d1, d1, a1);
        a2 = fmaf(d2, d2, a2);
        a3 = fmaf(d3, d3, a3);
    }
    float acc = (a0 + a1) + (a2 + a3);
#pragma unroll
    for (int o = 16; o > 0; o >>= 1)
        acc += __shfl_xor_sync(0xffffffffu, acc, o);

    __shared__ float sh[WARPS_PER_BLOCK];
    if (lane == 0)
        sh[wid] = fminf(fmaxf(acc, 1e-12f), 1e12f);   // clip diagonal entry
    __syncthreads();

    if (threadIdx.x == 0) {
        // fixed-order deterministic block sum (8 values)
        float bs = 0.0f;
#pragma unroll
        for (int w = 0; w < WARPS_PER_BLOCK; w++) bs += sh[w];

        // ONE atomic: accumulate Q.26 sum AND bump the block counter.
        unsigned long long q =
            (unsigned long long)__double2ll_rn((double)bs * FIX_SCALE);
        unsigned long long old =
            atomicAdd(&g_isum, q + (1ULL << CNT_SHIFT));

        if ((old >> CNT_SHIFT) == (unsigned long long)(GRID_BLOCKS - 1)) {
            // 512th arrival: grand total already in hand — no read-back.
            unsigned long long tot = (old & SUM_MASK) + q;
            double t = (double)tot * (1.0 / FIX_SCALE);
            out[0] = (float)(t / (double)BATCH + (double)(NUMC - 1) * 1e-12);
            g_isum = 0ULL;   // replay-safe reset (all contributions landed)
        }
    }
}

extern "C" void kernel_launch(void* const* d_in, const int* in_sizes, int n_in,
                              void* d_out, int out_size) {
    const float* x       = (const float*)d_in[0];
    const int*   labels  = (const int*)  d_in[1];
    const float* centers = (const float*)d_in[2];
    float*       out     = (float*)d_out;

    center_loss_kernel<<<GRID_BLOCKS, BLOCK_THREADS>>>(x, labels, centers, out);
}